// round 11
// baseline (speedup 1.0000x reference)
#include <cuda_runtime.h>

#define CHUNKS 32
#define TPB 256
#define FIN_SPLIT 4
#define MAXB 64
#define MAXNCOL 4   // supports D up to TPB*4*MAXNCOL = 4096

// Scratch: partial sums [B, CHUNKS, D]. 16 MB static (needs 8 MB here).
__device__ float g_partial[1 << 22];
__device__ float g_ss[MAXB * FIN_SPLIT]; // per-(b, finblk) squared-norm partials
__device__ int   g_cnt[MAXB];            // partial-completion counters (target CHUNKS)
__device__ int   g_nc[MAXB];             // ss-publication counters (target FIN_SPLIT)
__device__ int   g_fin[MAXB];            // finalize-exit counters (for reset)
// Zero-initialized at load; reset by the last finalize block of each sequence
// every replay, so the kernel is replay-safe under graph capture.

__global__ void __launch_bounds__(TPB, 4) pool_fused_kernel(
    const float* __restrict__ hs,
    const int* __restrict__ plens,
    const int* __restrict__ ilens,
    float* __restrict__ out,
    int D)
{
    const int b     = blockIdx.x;
    const int chunk = blockIdx.y;

    long start = 0;
    for (int i = 0; i < b; ++i) start += plens[i];

    const int pl = plens[b];
    const int il = ilens[b];
    const int n  = pl - il;  // valid token count

    const int t0 = (int)((long)chunk * n / CHUNKS);
    const int t1 = (int)((long)(chunk + 1) * n / CHUNKS);

    const int ncol = D / (TPB * 4);       // column slots per thread (<= MAXNCOL)
    const int tid4 = threadIdx.x * 4;

    // ------------- Phase 1: contiguous streaming partial sum ------------
    {
        const float* base = hs + (start + il) * (long)D + tid4;

        float4 acc[MAXNCOL];
        #pragma unroll
        for (int k = 0; k < MAXNCOL; ++k)
            acc[k] = make_float4(0.f, 0.f, 0.f, 0.f);

        int t = t0;
        // Two full rows per iteration: the block touches 2*D*4 contiguous
        // bytes per step -> each block is one perfectly sequential stream.
        for (; t + 2 <= t1; t += 2) {
            const float* r0 = base + (long)t * D;
            const float* r1 = r0 + D;
            float4 v0[MAXNCOL], v1[MAXNCOL];
            #pragma unroll
            for (int k = 0; k < MAXNCOL; ++k) {
                if (k < ncol) {
                    v0[k] = __ldcs((const float4*)(r0 + k * (TPB * 4)));
                    v1[k] = __ldcs((const float4*)(r1 + k * (TPB * 4)));
                }
            }
            #pragma unroll
            for (int k = 0; k < MAXNCOL; ++k) {
                if (k < ncol) {
                    acc[k].x += v0[k].x + v1[k].x;
                    acc[k].y += v0[k].y + v1[k].y;
                    acc[k].z += v0[k].z + v1[k].z;
                    acc[k].w += v0[k].w + v1[k].w;
                }
            }
        }
        for (; t < t1; ++t) {
            const float* r0 = base + (long)t * D;
            #pragma unroll
            for (int k = 0; k < MAXNCOL; ++k) {
                if (k < ncol) {
                    float4 v = __ldcs((const float4*)(r0 + k * (TPB * 4)));
                    acc[k].x += v.x; acc[k].y += v.y;
                    acc[k].z += v.z; acc[k].w += v.w;
                }
            }
        }

        float* o = g_partial + ((long)b * CHUNKS + chunk) * D + tid4;
        #pragma unroll
        for (int k = 0; k < MAXNCOL; ++k)
            if (k < ncol)
                *(float4*)(o + k * (TPB * 4)) = acc[k];
    }

    // Publish completion of this partial block.
    __syncthreads();
    __threadfence();
    if (threadIdx.x == 0)
        atomicAdd(&g_cnt[b], 1);

    // ------------- Phase 2: finalize (chunk < FIN_SPLIT blocks) ---------
    if (chunk >= FIN_SPLIT) return;

    if (threadIdx.x == 0) {
        while (*(volatile int*)&g_cnt[b] != CHUNKS) __nanosleep(64);
    }
    __syncthreads();

    const int fcolsz = D / FIN_SPLIT;              // columns per finalize block
    const int fcol   = chunk * fcolsz + tid4;      // this thread's column
    const bool colOK = (tid4 < fcolsz);

    const float inv = 1.0f / (float)n;
    float4 mean = make_float4(0.f, 0.f, 0.f, 0.f);
    float ss_local = 0.f;

    if (colOK) {
        const float* pb = g_partial + (long)b * CHUNKS * D + fcol;
        float4 s0 = make_float4(0.f, 0.f, 0.f, 0.f);
        float4 s1 = make_float4(0.f, 0.f, 0.f, 0.f);
        #pragma unroll 4
        for (int ch = 0; ch < CHUNKS; ch += 2) {
            float4 v = __ldcg((const float4*)(pb + (long)ch * D));
            float4 w = __ldcg((const float4*)(pb + (long)(ch + 1) * D));
            s0.x += v.x; s0.y += v.y; s0.z += v.z; s0.w += v.w;
            s1.x += w.x; s1.y += w.y; s1.z += w.z; s1.w += w.w;
        }
        mean.x = (s0.x + s1.x) * inv;
        mean.y = (s0.y + s1.y) * inv;
        mean.z = (s0.z + s1.z) * inv;
        mean.w = (s0.w + s1.w) * inv;
        ss_local = mean.x * mean.x + mean.y * mean.y +
                   mean.z * mean.z + mean.w * mean.w;
    }

    // Block reduction of ss_local (8 warps).
    __shared__ float red[TPB / 32];
    unsigned mask = 0xFFFFFFFFu;
    float ss = ss_local;
    #pragma unroll
    for (int off = 16; off > 0; off >>= 1)
        ss += __shfl_xor_sync(mask, ss, off);
    const int lane = threadIdx.x & 31;
    const int wid  = threadIdx.x >> 5;
    if (lane == 0) red[wid] = ss;
    __syncthreads();

    if (threadIdx.x == 0) {
        float v = 0.f;
        #pragma unroll
        for (int i = 0; i < TPB / 32; ++i) v += red[i];
        g_ss[b * FIN_SPLIT + chunk] = v;
        __threadfence();
        atomicAdd(&g_nc[b], 1);
        while (*(volatile int*)&g_nc[b] != FIN_SPLIT) __nanosleep(32);
    }
    __syncthreads();

    // Deterministic fixed-order sum of the per-finblk partials.
    float total = 0.f;
    #pragma unroll
    for (int i = 0; i < FIN_SPLIT; ++i)
        total += *(volatile float*)&g_ss[b * FIN_SPLIT + i];

    const float r = 1.0f / fmaxf(sqrtf(total), 1e-12f);

    if (colOK) {
        mean.x *= r; mean.y *= r; mean.z *= r; mean.w *= r;
        *(float4*)(out + (long)b * D + fcol) = mean;
    }

    // Reset counters for the next replay: last finalize block of b does it.
    __syncthreads();
    if (threadIdx.x == 0) {
        int old = atomicAdd(&g_fin[b], 1);
        if (old == FIN_SPLIT - 1) {
            g_cnt[b] = 0;
            g_nc[b]  = 0;
            g_fin[b] = 0;
            __threadfence();
        }
    }
}

// ---------------------------------------------------------------------------
extern "C" void kernel_launch(void* const* d_in, const int* in_sizes, int n_in,
                              void* d_out, int out_size)
{
    const float* hs    = (const float*)d_in[0];
    const int*   plens = (const int*)d_in[1];
    const int*   ilens = (const int*)d_in[2];
    float*       out   = (float*)d_out;

    const int B = in_sizes[1];
    const int D = out_size / B;

    dim3 grid(B, CHUNKS);
    pool_fused_kernel<<<grid, TPB>>>(hs, plens, ilens, out, D);
}

// round 12
// speedup vs baseline: 1.0140x; 1.0140x over previous
#include <cuda_runtime.h>

#define CHUNKS 8
#define TPB 256
#define MAXB 64
#define MAXDBLK 8

// Scratch (zero-initialized at load).
__device__ float g_partial[1 << 22];      // [B][CHUNKS][D] partial sums (2 MB used)
__device__ float g_mean[1 << 19];         // [B][D] mean scratch
__device__ float g_ss[MAXB * MAXDBLK];    // per-(b,dblk) squared-norm partials
__device__ int   g_cnt[MAXB * MAXDBLK];   // per-(b,dblk) chunk completion counters
__device__ int   g_nc[MAXB];              // per-b dblk-reduction completion counters
// Counters are reset by the final block of each sequence every call -> replay-safe.

__global__ void __launch_bounds__(TPB) pool_fused_kernel(
    const float* __restrict__ hs,
    const int* __restrict__ plens,
    const int* __restrict__ ilens,
    float* __restrict__ out,
    int D, int dblks)
{
    const int b     = blockIdx.x;
    const int chunk = blockIdx.y;
    const int dblk  = blockIdx.z;

    long start = 0;
    for (int i = 0; i < b; ++i) start += plens[i];

    const int pl = plens[b];
    const int il = ilens[b];
    const int n  = pl - il;  // valid token count

    const int t0 = (int)((long)chunk * n / CHUNKS);
    const int t1 = (int)((long)(chunk + 1) * n / CHUNKS);

    const int col = dblk * (TPB * 4) + threadIdx.x * 4;
    const bool colOK = (col < D);

    // ---------------- Phase 1: streaming partial sum (R2 loop) ----------
    if (colOK) {
        const float* base = hs + (start + il) * (long)D + col;

        float4 acc0 = make_float4(0.f, 0.f, 0.f, 0.f);
        float4 acc1 = make_float4(0.f, 0.f, 0.f, 0.f);

        int t = t0;
        for (; t + 8 <= t1; t += 8) {
            float4 v0 = __ldcs((const float4*)(base + (long)(t + 0) * D));
            float4 v1 = __ldcs((const float4*)(base + (long)(t + 1) * D));
            float4 v2 = __ldcs((const float4*)(base + (long)(t + 2) * D));
            float4 v3 = __ldcs((const float4*)(base + (long)(t + 3) * D));
            float4 v4 = __ldcs((const float4*)(base + (long)(t + 4) * D));
            float4 v5 = __ldcs((const float4*)(base + (long)(t + 5) * D));
            float4 v6 = __ldcs((const float4*)(base + (long)(t + 6) * D));
            float4 v7 = __ldcs((const float4*)(base + (long)(t + 7) * D));
            acc0.x += (v0.x + v1.x) + (v2.x + v3.x);
            acc0.y += (v0.y + v1.y) + (v2.y + v3.y);
            acc0.z += (v0.z + v1.z) + (v2.z + v3.z);
            acc0.w += (v0.w + v1.w) + (v2.w + v3.w);
            acc1.x += (v4.x + v5.x) + (v6.x + v7.x);
            acc1.y += (v4.y + v5.y) + (v6.y + v7.y);
            acc1.z += (v4.z + v5.z) + (v6.z + v7.z);
            acc1.w += (v4.w + v5.w) + (v6.w + v7.w);
        }
        for (; t < t1; ++t) {
            float4 v = __ldcs((const float4*)(base + (long)t * D));
            acc0.x += v.x; acc0.y += v.y; acc0.z += v.z; acc0.w += v.w;
        }
        acc0.x += acc1.x; acc0.y += acc1.y;
        acc0.z += acc1.z; acc0.w += acc1.w;

        float* o = g_partial + ((long)b * CHUNKS + chunk) * D + col;
        *(float4*)o = acc0;
    }

    // ------------- Election 1: last chunk for (b, dblk) reduces ---------
    __shared__ int s_last;
    __syncthreads();
    __threadfence();
    if (threadIdx.x == 0) {
        int old = atomicAdd(&g_cnt[b * MAXDBLK + dblk], 1);
        s_last = (old == CHUNKS - 1);
    }
    __syncthreads();
    if (!s_last) return;
    __threadfence();  // acquire: make peers' g_partial writes visible

    // ------------- Phase 2: chunk reduction for this (b, dblk) ----------
    const float inv = 1.0f / (float)n;
    float4 mean = make_float4(0.f, 0.f, 0.f, 0.f);
    float ss_local = 0.f;

    if (colOK) {
        const float* pb = g_partial + (long)b * CHUNKS * D + col;
        float4 s0 = make_float4(0.f, 0.f, 0.f, 0.f);
        float4 s1 = make_float4(0.f, 0.f, 0.f, 0.f);
        #pragma unroll
        for (int ch = 0; ch < CHUNKS; ch += 2) {
            float4 v = __ldcg((const float4*)(pb + (long)ch * D));
            float4 w = __ldcg((const float4*)(pb + (long)(ch + 1) * D));
            s0.x += v.x; s0.y += v.y; s0.z += v.z; s0.w += v.w;
            s1.x += w.x; s1.y += w.y; s1.z += w.z; s1.w += w.w;
        }
        mean.x = (s0.x + s1.x) * inv;
        mean.y = (s0.y + s1.y) * inv;
        mean.z = (s0.z + s1.z) * inv;
        mean.w = (s0.w + s1.w) * inv;
        ss_local = mean.x * mean.x + mean.y * mean.y +
                   mean.z * mean.z + mean.w * mean.w;
        *(float4*)(g_mean + (long)b * D + col) = mean;
    }

    // Block reduction of ss_local (8 warps).
    __shared__ float red[TPB / 32];
    unsigned mask = 0xFFFFFFFFu;
    float ss = ss_local;
    #pragma unroll
    for (int off = 16; off > 0; off >>= 1)
        ss += __shfl_xor_sync(mask, ss, off);
    const int lane = threadIdx.x & 31;
    const int wid  = threadIdx.x >> 5;
    if (lane == 0) red[wid] = ss;
    __syncthreads();

    // ------------- Election 2: last dblk for b finalizes -----------------
    __shared__ int s_lastb;
    if (threadIdx.x == 0) {
        float v = 0.f;
        #pragma unroll
        for (int i = 0; i < TPB / 32; ++i) v += red[i];
        g_ss[b * MAXDBLK + dblk] = v;
        __threadfence();
        int old = atomicAdd(&g_nc[b], 1);
        s_lastb = (old == dblks - 1);
    }
    __syncthreads();
    if (!s_lastb) return;
    __threadfence();  // acquire: peers' g_mean / g_ss writes visible

    // ------------- Phase 3: normalize + write output for b --------------
    float total = 0.f;
    for (int i = 0; i < dblks; ++i)          // deterministic fixed order
        total += g_ss[b * MAXDBLK + i];
    const float r = 1.0f / fmaxf(sqrtf(total), 1e-12f);

    for (int c = threadIdx.x * 4; c < D; c += TPB * 4) {
        float4 m = *(const float4*)(g_mean + (long)b * D + c);
        m.x *= r; m.y *= r; m.z *= r; m.w *= r;
        *(float4*)(out + (long)b * D + c) = m;
    }

    // ------------- Reset counters for next replay ------------------------
    // Safe: all blocks of sequence b have finished (counters hit targets).
    __syncthreads();
    if (threadIdx.x == 0) {
        #pragma unroll
        for (int i = 0; i < MAXDBLK; ++i)
            g_cnt[b * MAXDBLK + i] = 0;
        g_nc[b] = 0;
        __threadfence();
    }
}

// ---------------------------------------------------------------------------
extern "C" void kernel_launch(void* const* d_in, const int* in_sizes, int n_in,
                              void* d_out, int out_size)
{
    const float* hs    = (const float*)d_in[0];
    const int*   plens = (const int*)d_in[1];
    const int*   ilens = (const int*)d_in[2];
    float*       out   = (float*)d_out;

    const int B = in_sizes[1];
    const int D = out_size / B;

    const int dblks = (D + TPB * 4 - 1) / (TPB * 4);   // 1024 cols per block

    dim3 grid(B, CHUNKS, dblks);
    pool_fused_kernel<<<grid, TPB>>>(hs, plens, ilens, out, D, dblks);
}

// round 14
// speedup vs baseline: 1.0331x; 1.0188x over previous
#include <cuda_runtime.h>

#define CHUNKS 8
#define TPB 256
#define MAXB 64
#define MAXDBLK 8

// Scratch (zero-initialized at load).
__device__ float g_partial[1 << 22];      // [B][CHUNKS][D] partial sums (2 MB used)
__device__ float g_mean[1 << 19];         // [B][D] mean scratch
__device__ float g_ss[MAXB * MAXDBLK];    // per-(b,dblk) squared-norm partials
__device__ int   g_cnt[MAXB * MAXDBLK];   // per-(b,dblk) chunk completion counters
__device__ int   g_nc[MAXB];              // per-b dblk-reduction completion counters
// Counters are reset by the final block of each sequence every call -> replay-safe.

__global__ void __launch_bounds__(TPB) pool_fused_kernel(
    const float* __restrict__ hs,
    const int* __restrict__ plens,
    const int* __restrict__ ilens,
    float* __restrict__ out,
    int D, int dblks)
{
    const int b     = blockIdx.x;
    const int chunk = blockIdx.y;
    const int dblk  = blockIdx.z;

    long start = 0;
    for (int i = 0; i < b; ++i) start += plens[i];

    const int pl = plens[b];
    const int il = ilens[b];
    const int n  = pl - il;  // valid token count

    const int t0 = (int)((long)chunk * n / CHUNKS);
    const int t1 = (int)((long)(chunk + 1) * n / CHUNKS);

    const int col = dblk * (TPB * 4) + threadIdx.x * 4;
    const bool colOK = (col < D);

    // ---------------- Phase 1: streaming partial sum (R2 loop) ----------
    if (colOK) {
        const float* base = hs + (start + il) * (long)D + col;

        float4 acc0 = make_float4(0.f, 0.f, 0.f, 0.f);
        float4 acc1 = make_float4(0.f, 0.f, 0.f, 0.f);

        int t = t0;
        for (; t + 8 <= t1; t += 8) {
            float4 v0 = __ldcs((const float4*)(base + (long)(t + 0) * D));
            float4 v1 = __ldcs((const float4*)(base + (long)(t + 1) * D));
            float4 v2 = __ldcs((const float4*)(base + (long)(t + 2) * D));
            float4 v3 = __ldcs((const float4*)(base + (long)(t + 3) * D));
            float4 v4 = __ldcs((const float4*)(base + (long)(t + 4) * D));
            float4 v5 = __ldcs((const float4*)(base + (long)(t + 5) * D));
            float4 v6 = __ldcs((const float4*)(base + (long)(t + 6) * D));
            float4 v7 = __ldcs((const float4*)(base + (long)(t + 7) * D));
            acc0.x += (v0.x + v1.x) + (v2.x + v3.x);
            acc0.y += (v0.y + v1.y) + (v2.y + v3.y);
            acc0.z += (v0.z + v1.z) + (v2.z + v3.z);
            acc0.w += (v0.w + v1.w) + (v2.w + v3.w);
            acc1.x += (v4.x + v5.x) + (v6.x + v7.x);
            acc1.y += (v4.y + v5.y) + (v6.y + v7.y);
            acc1.z += (v4.z + v5.z) + (v6.z + v7.z);
            acc1.w += (v4.w + v5.w) + (v6.w + v7.w);
        }
        for (; t < t1; ++t) {
            float4 v = __ldcs((const float4*)(base + (long)t * D));
            acc0.x += v.x; acc0.y += v.y; acc0.z += v.z; acc0.w += v.w;
        }
        acc0.x += acc1.x; acc0.y += acc1.y;
        acc0.z += acc1.z; acc0.w += acc1.w;

        float* o = g_partial + ((long)b * CHUNKS + chunk) * D + col;
        *(float4*)o = acc0;
    }

    // ------------- Election 1: last chunk for (b, dblk) reduces ---------
    __shared__ int s_last;
    __syncthreads();
    __threadfence();
    if (threadIdx.x == 0) {
        int old = atomicAdd(&g_cnt[b * MAXDBLK + dblk], 1);
        s_last = (old == CHUNKS - 1);
    }
    __syncthreads();
    if (!s_last) return;
    __threadfence();  // acquire: make peers' g_partial writes visible

    // ------------- Phase 2: chunk reduction for this (b, dblk) ----------
    const float inv = 1.0f / (float)n;
    float4 mean = make_float4(0.f, 0.f, 0.f, 0.f);
    float ss_local = 0.f;

    if (colOK) {
        const float* pb = g_partial + (long)b * CHUNKS * D + col;
        float4 s0 = make_float4(0.f, 0.f, 0.f, 0.f);
        float4 s1 = make_float4(0.f, 0.f, 0.f, 0.f);
        #pragma unroll
        for (int ch = 0; ch < CHUNKS; ch += 2) {
            float4 v = __ldcg((const float4*)(pb + (long)ch * D));
            float4 w = __ldcg((const float4*)(pb + (long)(ch + 1) * D));
            s0.x += v.x; s0.y += v.y; s0.z += v.z; s0.w += v.w;
            s1.x += w.x; s1.y += w.y; s1.z += w.z; s1.w += w.w;
        }
        mean.x = (s0.x + s1.x) * inv;
        mean.y = (s0.y + s1.y) * inv;
        mean.z = (s0.z + s1.z) * inv;
        mean.w = (s0.w + s1.w) * inv;
        ss_local = mean.x * mean.x + mean.y * mean.y +
                   mean.z * mean.z + mean.w * mean.w;
        *(float4*)(g_mean + (long)b * D + col) = mean;
    }

    // Block reduction of ss_local (8 warps).
    __shared__ float red[TPB / 32];
    unsigned mask = 0xFFFFFFFFu;
    float ss = ss_local;
    #pragma unroll
    for (int off = 16; off > 0; off >>= 1)
        ss += __shfl_xor_sync(mask, ss, off);
    const int lane = threadIdx.x & 31;
    const int wid  = threadIdx.x >> 5;
    if (lane == 0) red[wid] = ss;
    __syncthreads();

    // ------------- Election 2: last dblk for b finalizes -----------------
    __shared__ int s_lastb;
    if (threadIdx.x == 0) {
        float v = 0.f;
        #pragma unroll
        for (int i = 0; i < TPB / 32; ++i) v += red[i];
        g_ss[b * MAXDBLK + dblk] = v;
        __threadfence();
        int old = atomicAdd(&g_nc[b], 1);
        s_lastb = (old == dblks - 1);
    }
    __syncthreads();
    if (!s_lastb) return;
    __threadfence();  // acquire: peers' g_mean / g_ss writes visible

    // ------------- Phase 3: normalize + write output for b --------------
    float total = 0.f;
    for (int i = 0; i < dblks; ++i)          // deterministic fixed order
        total += g_ss[b * MAXDBLK + i];
    const float r = 1.0f / fmaxf(sqrtf(total), 1e-12f);

    for (int c = threadIdx.x * 4; c < D; c += TPB * 4) {
        float4 m = *(const float4*)(g_mean + (long)b * D + c);
        m.x *= r; m.y *= r; m.z *= r; m.w *= r;
        *(float4*)(out + (long)b * D + c) = m;
    }

    // ------------- Reset counters for next replay ------------------------
    // Safe: all blocks of sequence b have finished (counters hit targets).
    __syncthreads();
    if (threadIdx.x == 0) {
        #pragma unroll
        for (int i = 0; i < MAXDBLK; ++i)
            g_cnt[b * MAXDBLK + i] = 0;
        g_nc[b] = 0;
        __threadfence();
    }
}

// ---------------------------------------------------------------------------
extern "C" void kernel_launch(void* const* d_in, const int* in_sizes, int n_in,
                              void* d_out, int out_size)
{
    const float* hs    = (const float*)d_in[0];
    const int*   plens = (const int*)d_in[1];
    const int*   ilens = (const int*)d_in[2];
    float*       out   = (float*)d_out;

    const int B = in_sizes[1];
    const int D = out_size / B;

    const int dblks = (D + TPB * 4 - 1) / (TPB * 4);   // 1024 cols per block

    dim3 grid(B, CHUNKS, dblks);
    pool_fused_kernel<<<grid, TPB>>>(hs, plens, ilens, out, D, dblks);
}